// round 9
// baseline (speedup 1.0000x reference)
#include <cuda_runtime.h>
#include <cuda_bf16.h>
#include <cstdint>

#define FULL 0xffffffffu
#define EPS 1e-8f
#define WARPS_PER_BLOCK 8
#define THREADS (WARPS_PER_BLOCK * 32)
#define BLOCKS_PER_SM 8
#define NUM_SMS 148
#define N_MAX 100000
#define M_MAX 50000

// Packed scratch (filled by prepass): points and queries as float4.
__device__ float4 g_points4[N_MAX];
__device__ float4 g_q4[M_MAX];

__device__ __forceinline__ float fast_sqrt(float x) {
    float r;
    asm("sqrt.approx.ftz.f32 %0, %1;" : "=f"(r) : "f"(x));
    return r;
}

__device__ __forceinline__ void cp_async16(unsigned smem_addr, const void* gptr) {
    asm volatile("cp.async.cg.shared.global [%0], [%1], 16;\n"
                 :: "r"(smem_addr), "l"(gptr));
}
__device__ __forceinline__ void cp_commit() {
    asm volatile("cp.async.commit_group;\n" ::: "memory");
}
__device__ __forceinline__ void cp_wait1() {
    asm volatile("cp.async.wait_group 1;\n" ::: "memory");
}

__global__ void pack_kernel(const float* __restrict__ points, int N,
                            const float* __restrict__ q_coords, int M) {
    int i = blockIdx.x * blockDim.x + threadIdx.x;
    if (i < N)
        g_points4[i] = make_float4(points[3 * i + 0], points[3 * i + 1],
                                   points[3 * i + 2], 0.0f);
    if (i < M)
        g_q4[i] = make_float4(q_coords[3 * i + 0], q_coords[3 * i + 1],
                              q_coords[3 * i + 2], 0.0f);
}

__global__ __launch_bounds__(THREADS, BLOCKS_PER_SM)
void gib_kernel(const int* __restrict__ support_idxs,
                const float* __restrict__ cy_radius,
                const float* __restrict__ disk_radius,
                const float* __restrict__ disk_width,
                const float* __restrict__ cone_radius,
                const float* __restrict__ cone_inc,
                const float* __restrict__ ellip_radii,
                const float* __restrict__ lambdas,
                float* __restrict__ out,
                int M, int P /* number of query pairs */)
{
    __shared__ float4 s_coef[32];
    __shared__ float  s_inc[32];
    __shared__ float  s_lamT[16][36];                  // transposed, padded, /K folded
    __shared__ float4 s_tile[WARPS_PER_BLOCK][2][64];  // double-buffered gathered pts
    // NOTE: survivor compaction + acc staging ALIAS s_tile[wid][buf] — that
    // buffer's point data is dead once pa/pb are in registers, and the next
    // cp.async into it is only issued after the epilogue __syncwarp.

    int tid = threadIdx.x;

    if (tid < 32) {
        int kind = tid >> 3;
        int g    = tid & 7;
        float a = 0.f, b = 0.f, c = 0.f, e = 0.f, inc = 0.f;
        if (kind == 0) {                 // cylinder
            float r = cy_radius[g];
            float v = -0.5f / (r * r + EPS);
            a = v; b = v;
        } else if (kind == 1) {          // cone
            float r = cone_radius[g];
            e = -0.5f / (r * r + EPS);
            inc = cone_inc[g];
        } else if (kind == 2) {          // disk
            float r = disk_radius[g];
            float w = disk_width[g];
            float v = -0.5f / (r * r + EPS);
            a = v; b = v;
            c = -0.5f / (w * w + EPS);
        } else {                         // ellipsoid
            float ex = ellip_radii[g * 3 + 0];
            float ey = ellip_radii[g * 3 + 1];
            float ez = ellip_radii[g * 3 + 2];
            a = -0.5f / (ex * ex + EPS);
            b = -0.5f / (ey * ey + EPS);
            c = -0.5f / (ez * ez + EPS);
        }
        s_coef[tid] = make_float4(a, b, c, e);
        s_inc[tid] = inc;
    }
    for (int i = tid; i < 32 * 16; i += THREADS) {
        int j = i >> 4, o = i & 15;
        s_lamT[o][j] = lambdas[i] * (1.0f / 32.0f);    // fold masked-mean 1/K
    }
    __syncthreads();

    int lane = tid & 31;
    int wid  = tid >> 5;
    unsigned ltmask = (1u << lane) - 1u;

    float4 cf  = s_coef[lane];
    float  inc = s_inc[lane];

    int gw     = blockIdx.x * WARPS_PER_BLOCK + wid;
    int stride = gridDim.x * WARPS_PER_BLOCK;

    int p = gw;
    if (p >= P) return;

    unsigned tile0 = (unsigned)__cvta_generic_to_shared(&s_tile[wid][0][0]);
    unsigned tile1 = (unsigned)__cvta_generic_to_shared(&s_tile[wid][1][0]);

    // ---- Prologue: stage pair p into buf0 ----
    {
        int m0 = 2 * p;
        int m1 = min(2 * p + 1, M - 1);
        int ia = __ldg(&support_idxs[m0 * 32 + lane]);
        int ib = __ldg(&support_idxs[m1 * 32 + lane]);
        cp_async16(tile0 + lane * 16,        &g_points4[ia]);
        cp_async16(tile0 + (32 + lane) * 16, &g_points4[ib]);
    }
    cp_commit();

    // idx for pair p+stride
    int pn = p + stride;
    int ian = 0, ibn = 0;
    if (pn < P) {
        ian = __ldg(&support_idxs[(2 * pn) * 32 + lane]);
        ibn = __ldg(&support_idxs[min(2 * pn + 1, M - 1) * 32 + lane]);
    }

    int buf = 0;
    while (p < P) {
        // ---- Stage next pair into other buffer ----
        unsigned tnext = buf ? tile0 : tile1;
        if (pn < P) {
            cp_async16(tnext + lane * 16,        &g_points4[ian]);
            cp_async16(tnext + (32 + lane) * 16, &g_points4[ibn]);
        }
        cp_commit();

        int pnn = pn + stride;
        if (pnn < P) {
            ian = __ldg(&support_idxs[(2 * pnn) * 32 + lane]);
            ibn = __ldg(&support_idxs[min(2 * pnn + 1, M - 1) * 32 + lane]);
        }

        // ---- Current pair ready after wait (1 group still in flight).
        // Each lane reads only SMEM its own cp.asyncs wrote -> no syncwarp.
        cp_wait1();

        int m0 = 2 * p;
        int m1 = min(2 * p + 1, M - 1);
        float4* curt = &s_tile[wid][buf][0];
        float4 pa = curt[lane];
        float4 pb = curt[32 + lane];
        float4 qa = g_q4[m0];          // broadcast, L1-resident
        float4 qb = g_q4[m1];

        float xa = pa.x - qa.x, ya = pa.y - qa.y, za = pa.z - qa.z;
        float xb = pb.x - qb.x, yb = pb.y - qb.y, zb = pb.z - qb.z;
        float x2a = xa * xa, y2a = ya * ya;
        float x2b = xb * xb, y2b = yb * yb;
        float xy2a = x2a + y2a, xy2b = x2b + y2b;
        float d2a = xy2a + za * za;
        float d2b = xy2b + zb * zb;
        float rxya = fast_sqrt(xy2a + EPS);
        float rxyb = fast_sqrt(xy2b + EPS);

        bool alive0 = (d2a <= 1.0f);
        bool alive1 = (d2b <= 1.0f) && (m1 == 2 * p + 1);
        // Ballots are warp-collective: every lane has consumed pa/pb before
        // any lane proceeds -> safe to overwrite curt (alias) below.
        unsigned b0 = __ballot_sync(FULL, alive0);
        unsigned b1 = __ballot_sync(FULL, alive1);
        int n0 = __popc(b0);
        int n1 = __popc(b1);

        float4* surv = curt;           // alias: slots [0..31]=q0, [32..63]=q1
        if (alive0) surv[__popc(b0 & ltmask)]      = make_float4(x2a, y2a, za, rxya);
        if (alive1) surv[32 + __popc(b1 & ltmask)] = make_float4(x2b, y2b, zb, rxyb);
        __syncwarp();

        float acc0 = 0.0f, acc1 = 0.0f;
        int nmax = max(n0, n1);
        #pragma unroll 2
        for (int j = 0; j < nmax; j++) {
            if (j < n0) {
                float4 v = surv[j];
                float dd = fmaf(-inc, v.z, v.w);
                float t = fmaf(cf.x, v.x,
                          fmaf(cf.y, v.y,
                          fmaf(cf.z, v.z * v.z, (cf.w * dd) * dd)));
                acc0 += __expf(t);
            }
            if (j < n1) {
                float4 v = surv[32 + j];
                float dd = fmaf(-inc, v.z, v.w);
                float t = fmaf(cf.x, v.x,
                          fmaf(cf.y, v.y,
                          fmaf(cf.z, v.z * v.z, (cf.w * dd) * dd)));
                acc1 += __expf(t);
            }
        }
        __syncwarp();

        // Stage accumulators (alias again — survivor data now dead).
        float* accp = (float*)surv;
        accp[lane]      = acc0;
        accp[32 + lane] = acc1;
        __syncwarp();

        int qsel = lane >> 4;
        int o    = lane & 15;
        int mst  = qsel ? (2 * p + 1) : m0;
        if (mst < M) {
            const float* arow = accp + qsel * 32;
            float ot = 0.0f;
            #pragma unroll
            for (int j = 0; j < 32; j += 4) {
                float4 lam4 = *(const float4*)&s_lamT[o][j];
                float4 a4   = *(const float4*)&arow[j];
                ot = fmaf(a4.x, lam4.x,
                     fmaf(a4.y, lam4.y,
                     fmaf(a4.z, lam4.z,
                     fmaf(a4.w, lam4.w, ot))));
            }
            out[mst * 16 + o] = ot;
        }
        __syncwarp();   // epilogue reads done before next cp.async into curt

        // ---- Rotate ----
        p = pn; pn = pnn;
        buf ^= 1;
    }
}

extern "C" void kernel_launch(void* const* d_in, const int* in_sizes, int n_in,
                              void* d_out, int out_size) {
    const float* points       = (const float*)d_in[0];
    const float* q_coords     = (const float*)d_in[1];
    const int*   support_idxs = (const int*)  d_in[2];
    const float* cy_radius    = (const float*)d_in[3];
    const float* disk_radius  = (const float*)d_in[4];
    const float* disk_width   = (const float*)d_in[5];
    const float* cone_radius  = (const float*)d_in[6];
    const float* cone_inc     = (const float*)d_in[7];
    const float* ellip_radii  = (const float*)d_in[8];
    const float* lambdas      = (const float*)d_in[9];
    float* out = (float*)d_out;

    int N = in_sizes[0] / 3;   // points has N*3 elements
    int M = in_sizes[1] / 3;   // q_coords has M*3 elements
    int P = (M + 1) / 2;       // query pairs

    int packN = N > M ? N : M;
    pack_kernel<<<(packN + 255) / 256, 256>>>(points, N, q_coords, M);

    int maxBlocks = NUM_SMS * BLOCKS_PER_SM;
    int needBlocks = (P + WARPS_PER_BLOCK - 1) / WARPS_PER_BLOCK;
    int blocks = needBlocks < maxBlocks ? needBlocks : maxBlocks;
    gib_kernel<<<blocks, THREADS>>>(support_idxs,
                                    cy_radius, disk_radius, disk_width,
                                    cone_radius, cone_inc, ellip_radii,
                                    lambdas, out, M, P);
}

// round 10
// speedup vs baseline: 1.0015x; 1.0015x over previous
#include <cuda_runtime.h>
#include <cuda_bf16.h>
#include <cstdint>

#define FULL 0xffffffffu
#define EPS 1e-8f
#define WARPS_PER_BLOCK 8
#define THREADS (WARPS_PER_BLOCK * 32)
#define BLOCKS_PER_SM 7
#define NUM_SMS 148
#define N_MAX 100000
#define M_MAX 50000

// Packed scratch (filled by prepass): points and queries as float4.
__device__ float4 g_points4[N_MAX];
__device__ float4 g_q4[M_MAX];

__device__ __forceinline__ float fast_sqrt(float x) {
    float r;
    asm("sqrt.approx.ftz.f32 %0, %1;" : "=f"(r) : "f"(x));
    return r;
}

__device__ __forceinline__ void cp_async16(unsigned smem_addr, const void* gptr) {
    asm volatile("cp.async.cg.shared.global [%0], [%1], 16;\n"
                 :: "r"(smem_addr), "l"(gptr));
}
__device__ __forceinline__ void cp_commit() {
    asm volatile("cp.async.commit_group;\n" ::: "memory");
}
__device__ __forceinline__ void cp_wait2() {
    asm volatile("cp.async.wait_group 2;\n" ::: "memory");
}

__global__ void pack_kernel(const float* __restrict__ points, int N,
                            const float* __restrict__ q_coords, int M) {
    int i = blockIdx.x * blockDim.x + threadIdx.x;
    if (i < N)
        g_points4[i] = make_float4(points[3 * i + 0], points[3 * i + 1],
                                   points[3 * i + 2], 0.0f);
    if (i < M)
        g_q4[i] = make_float4(q_coords[3 * i + 0], q_coords[3 * i + 1],
                              q_coords[3 * i + 2], 0.0f);
}

__global__ __launch_bounds__(THREADS, BLOCKS_PER_SM)
void gib_kernel(const int* __restrict__ support_idxs,
                const float* __restrict__ cy_radius,
                const float* __restrict__ disk_radius,
                const float* __restrict__ disk_width,
                const float* __restrict__ cone_radius,
                const float* __restrict__ cone_inc,
                const float* __restrict__ ellip_radii,
                const float* __restrict__ lambdas,
                float* __restrict__ out,
                int M, int P /* number of query pairs */)
{
    __shared__ float4 s_coef[32];
    __shared__ float  s_inc[32];
    __shared__ float  s_lamT[16][36];                  // transposed, padded, /K folded
    __shared__ float4 s_tile[WARPS_PER_BLOCK][3][64];  // 3-deep ring of gathered pts
    // Survivor compaction + acc staging ALIAS the CURRENT ring buffer — its
    // point data is dead once pa/pb are in registers (ballot = convergence
    // point), and the next cp.async into that buffer is issued only on the
    // following iteration, after the epilogue __syncwarp.

    int tid = threadIdx.x;

    if (tid < 32) {
        int kind = tid >> 3;
        int g    = tid & 7;
        float a = 0.f, b = 0.f, c = 0.f, e = 0.f, inc = 0.f;
        if (kind == 0) {                 // cylinder
            float r = cy_radius[g];
            float v = -0.5f / (r * r + EPS);
            a = v; b = v;
        } else if (kind == 1) {          // cone
            float r = cone_radius[g];
            e = -0.5f / (r * r + EPS);
            inc = cone_inc[g];
        } else if (kind == 2) {          // disk
            float r = disk_radius[g];
            float w = disk_width[g];
            float v = -0.5f / (r * r + EPS);
            a = v; b = v;
            c = -0.5f / (w * w + EPS);
        } else {                         // ellipsoid
            float ex = ellip_radii[g * 3 + 0];
            float ey = ellip_radii[g * 3 + 1];
            float ez = ellip_radii[g * 3 + 2];
            a = -0.5f / (ex * ex + EPS);
            b = -0.5f / (ey * ey + EPS);
            c = -0.5f / (ez * ez + EPS);
        }
        s_coef[tid] = make_float4(a, b, c, e);
        s_inc[tid] = inc;
    }
    for (int i = tid; i < 32 * 16; i += THREADS) {
        int j = i >> 4, o = i & 15;
        s_lamT[o][j] = lambdas[i] * (1.0f / 32.0f);    // fold masked-mean 1/K
    }
    __syncthreads();

    int lane = tid & 31;
    int wid  = tid >> 5;
    unsigned ltmask = (1u << lane) - 1u;

    float4 cf  = s_coef[lane];
    float  inc = s_inc[lane];

    int gw     = blockIdx.x * WARPS_PER_BLOCK + wid;
    int stride = gridDim.x * WARPS_PER_BLOCK;

    int p0 = gw;
    if (p0 >= P) return;

    unsigned tbase = (unsigned)__cvta_generic_to_shared(&s_tile[wid][0][0]);
    // buffer k address = tbase + k*1024

    // ---- Prologue: issue stages 0 and 1, prefetch idx for stage 2 ----
    int ia = __ldg(&support_idxs[(2 * p0) * 32 + lane]);
    int ib = __ldg(&support_idxs[min(2 * p0 + 1, M - 1) * 32 + lane]);
    cp_async16(tbase + lane * 16,        &g_points4[ia]);
    cp_async16(tbase + (32 + lane) * 16, &g_points4[ib]);
    cp_commit();

    int p1 = p0 + stride;
    if (p1 < P) {
        ia = __ldg(&support_idxs[(2 * p1) * 32 + lane]);
        ib = __ldg(&support_idxs[min(2 * p1 + 1, M - 1) * 32 + lane]);
        cp_async16(tbase + 1024 + lane * 16,        &g_points4[ia]);
        cp_async16(tbase + 1024 + (32 + lane) * 16, &g_points4[ib]);
    }
    cp_commit();

    int p2pre = p0 + 2 * stride;
    if (p2pre < P) {
        ia = __ldg(&support_idxs[(2 * p2pre) * 32 + lane]);
        ib = __ldg(&support_idxs[min(2 * p2pre + 1, M - 1) * 32 + lane]);
    }

    int bcur = 0;    // buffer holding current pair
    int biss = 2;    // buffer for stage being issued (i+2)
    for (int p = p0; p < P; p += stride) {
        // ---- Issue stage p+2*stride into its ring slot ----
        int pc2 = p + 2 * stride;
        if (pc2 < P) {
            unsigned bufn = tbase + biss * 1024;
            cp_async16(bufn + lane * 16,        &g_points4[ia]);
            cp_async16(bufn + (32 + lane) * 16, &g_points4[ib]);
        }
        cp_commit();

        int pc3 = p + 3 * stride;
        if (pc3 < P) {
            ia = __ldg(&support_idxs[(2 * pc3) * 32 + lane]);
            ib = __ldg(&support_idxs[min(2 * pc3 + 1, M - 1) * 32 + lane]);
        }

        // ---- Current pair's group complete once ≤2 groups outstanding ----
        cp_wait2();

        int m0 = 2 * p;
        int m1 = min(2 * p + 1, M - 1);
        float4* curt = &s_tile[wid][bcur][0];
        float4 pa = curt[lane];
        float4 pb = curt[32 + lane];
        float4 qa = g_q4[m0];          // broadcast, L1-resident
        float4 qb = g_q4[m1];

        float xa = pa.x - qa.x, ya = pa.y - qa.y, za = pa.z - qa.z;
        float xb = pb.x - qb.x, yb = pb.y - qb.y, zb = pb.z - qb.z;
        float x2a = xa * xa, y2a = ya * ya;
        float x2b = xb * xb, y2b = yb * yb;
        float xy2a = x2a + y2a, xy2b = x2b + y2b;
        float d2a = xy2a + za * za;
        float d2b = xy2b + zb * zb;
        float rxya = fast_sqrt(xy2a + EPS);
        float rxyb = fast_sqrt(xy2b + EPS);

        bool alive0 = (d2a <= 1.0f);
        bool alive1 = (d2b <= 1.0f) && (m1 == 2 * p + 1);
        // Ballots are warp-collective: every lane has consumed pa/pb before
        // any lane proceeds -> safe to overwrite curt (alias) below.
        unsigned b0 = __ballot_sync(FULL, alive0);
        unsigned b1 = __ballot_sync(FULL, alive1);
        int n0 = __popc(b0);
        int n1 = __popc(b1);

        float4* surv = curt;           // alias: slots [0..31]=q0, [32..63]=q1
        if (alive0) surv[__popc(b0 & ltmask)]      = make_float4(x2a, y2a, za, rxya);
        if (alive1) surv[32 + __popc(b1 & ltmask)] = make_float4(x2b, y2b, zb, rxyb);
        __syncwarp();

        float acc0 = 0.0f, acc1 = 0.0f;
        int nmax = max(n0, n1);
        #pragma unroll 2
        for (int j = 0; j < nmax; j++) {
            if (j < n0) {
                float4 v = surv[j];
                float dd = fmaf(-inc, v.z, v.w);
                float t = fmaf(cf.x, v.x,
                          fmaf(cf.y, v.y,
                          fmaf(cf.z, v.z * v.z, (cf.w * dd) * dd)));
                acc0 += __expf(t);
            }
            if (j < n1) {
                float4 v = surv[32 + j];
                float dd = fmaf(-inc, v.z, v.w);
                float t = fmaf(cf.x, v.x,
                          fmaf(cf.y, v.y,
                          fmaf(cf.z, v.z * v.z, (cf.w * dd) * dd)));
                acc1 += __expf(t);
            }
        }
        __syncwarp();

        // Stage accumulators (alias again — survivor data now dead).
        float* accp = (float*)surv;
        accp[lane]      = acc0;
        accp[32 + lane] = acc1;
        __syncwarp();

        int qsel = lane >> 4;
        int o    = lane & 15;
        int mst  = qsel ? (2 * p + 1) : m0;
        if (mst < M) {
            const float* arow = accp + qsel * 32;
            float ot = 0.0f;
            #pragma unroll
            for (int j = 0; j < 32; j += 4) {
                float4 lam4 = *(const float4*)&s_lamT[o][j];
                float4 a4   = *(const float4*)&arow[j];
                ot = fmaf(a4.x, lam4.x,
                     fmaf(a4.y, lam4.y,
                     fmaf(a4.z, lam4.z,
                     fmaf(a4.w, lam4.w, ot))));
            }
            out[mst * 16 + o] = ot;
        }
        __syncwarp();   // epilogue reads done before next cp.async into curt

        // ---- Rotate ring ----
        bcur = (bcur == 2) ? 0 : bcur + 1;
        biss = (biss == 2) ? 0 : biss + 1;
    }
}

extern "C" void kernel_launch(void* const* d_in, const int* in_sizes, int n_in,
                              void* d_out, int out_size) {
    const float* points       = (const float*)d_in[0];
    const float* q_coords     = (const float*)d_in[1];
    const int*   support_idxs = (const int*)  d_in[2];
    const float* cy_radius    = (const float*)d_in[3];
    const float* disk_radius  = (const float*)d_in[4];
    const float* disk_width   = (const float*)d_in[5];
    const float* cone_radius  = (const float*)d_in[6];
    const float* cone_inc     = (const float*)d_in[7];
    const float* ellip_radii  = (const float*)d_in[8];
    const float* lambdas      = (const float*)d_in[9];
    float* out = (float*)d_out;

    int N = in_sizes[0] / 3;   // points has N*3 elements
    int M = in_sizes[1] / 3;   // q_coords has M*3 elements
    int P = (M + 1) / 2;       // query pairs

    int packN = N > M ? N : M;
    pack_kernel<<<(packN + 255) / 256, 256>>>(points, N, q_coords, M);

    int maxBlocks = NUM_SMS * BLOCKS_PER_SM;
    int needBlocks = (P + WARPS_PER_BLOCK - 1) / WARPS_PER_BLOCK;
    int blocks = needBlocks < maxBlocks ? needBlocks : maxBlocks;
    gib_kernel<<<blocks, THREADS>>>(support_idxs,
                                    cy_radius, disk_radius, disk_width,
                                    cone_radius, cone_inc, ellip_radii,
                                    lambdas, out, M, P);
}